// round 6
// baseline (speedup 1.0000x reference)
#include <cuda_runtime.h>

// Problem constants
#define Bn   4
#define Ln   1024
#define Cn   512
#define Hn   8
#define Dn   64
#define FCn  2048
#define NLn  4
#define Wn   4
#define Mrows (Bn * Ln)          // 4096
#define SCALEF 0.125f            // 64^-0.5
#define EPSF   1e-6f

// ---------------- scratch (static device memory; no allocations) -----------
__device__ float g_xt [Mrows * Cn];
__device__ float g_q  [Mrows * Cn];
__device__ float g_k  [Mrows * Cn];
__device__ float g_v  [Mrows * Cn];
__device__ float g_ao [Mrows * Cn];
__device__ float g_tmp[Mrows * Cn];
__device__ float g_h  [Mrows * FCn];

// ---------------- transpose in: x[B,C,L] -> xt[B,L,C], * mask --------------
__global__ void transpose_in(const float* __restrict__ x,
                             const float* __restrict__ mask,
                             float* __restrict__ xt) {
    __shared__ float tile[32][33];
    int b  = blockIdx.z;
    int c0 = blockIdx.y * 32, l0 = blockIdx.x * 32;
    int tx = threadIdx.x, ty = threadIdx.y;
    for (int i = ty; i < 32; i += 8)
        tile[i][tx] = x[((long)b * Cn + c0 + i) * Ln + l0 + tx];
    __syncthreads();
    for (int i = ty; i < 32; i += 8) {
        int l = l0 + i;
        xt[((long)b * Ln + l) * Cn + c0 + tx] = tile[tx][i] * mask[b * Ln + l];
    }
}

// ---------------- transpose out: xt[B,L,C] -> out[B,C,L], * mask -----------
__global__ void transpose_out(const float* __restrict__ xt,
                              const float* __restrict__ mask,
                              float* __restrict__ out) {
    __shared__ float tile[32][33];
    int b  = blockIdx.z;
    int c0 = blockIdx.y * 32, l0 = blockIdx.x * 32;
    int tx = threadIdx.x, ty = threadIdx.y;
    for (int i = ty; i < 32; i += 8)
        tile[i][tx] = xt[((long)b * Ln + l0 + i) * Cn + c0 + tx];
    __syncthreads();
    for (int i = ty; i < 32; i += 8)
        out[((long)b * Cn + c0 + i) * Ln + l0 + tx] = tile[tx][i] * mask[b * Ln + l0 + tx];
}

// ---------------- SGEMM NT: out[M,N] = A[M,K] @ Wt[N,K]^T, epilogues -------
// EPI 0: out = acc + bias
// EPI 1: out = (acc + bias) * alpha
// EPI 2: out = relu(acc*mr + bias) * mr     (mr = mask[row])   [FFN1]
// EPI 3: out = (acc + bias) * mr                                [FFN2]
template<int EPI>
__global__ void __launch_bounds__(256) sgemm_nt(
    const float* __restrict__ A, const float* __restrict__ Wt,
    const float* __restrict__ bias, const float* __restrict__ mask,
    float* __restrict__ out, int N, int K, float alpha) {
    __shared__ float As[16][132];
    __shared__ float Bs[16][132];
    const int tid = threadIdx.x;
    const int ty = tid >> 4, tx = tid & 15;
    const int row0 = blockIdx.y * 128, col0 = blockIdx.x * 128;
    const float* Ap = A  + (long)row0 * K;
    const float* Wp = Wt + (long)col0 * K;

    float acc[8][8];
#pragma unroll
    for (int i = 0; i < 8; i++)
#pragma unroll
        for (int j = 0; j < 8; j++) acc[i][j] = 0.f;

    for (int k0 = 0; k0 < K; k0 += 16) {
#pragma unroll
        for (int t = 0; t < 2; t++) {
            int f  = tid + t * 256;      // 0..511 (float4 index)
            int r  = f >> 2;             // 0..127
            int kc = (f & 3) << 2;       // 0,4,8,12
            float4 av = *reinterpret_cast<const float4*>(&Ap[(long)r * K + k0 + kc]);
            As[kc + 0][r] = av.x; As[kc + 1][r] = av.y;
            As[kc + 2][r] = av.z; As[kc + 3][r] = av.w;
            float4 bv = *reinterpret_cast<const float4*>(&Wp[(long)r * K + k0 + kc]);
            Bs[kc + 0][r] = bv.x; Bs[kc + 1][r] = bv.y;
            Bs[kc + 2][r] = bv.z; Bs[kc + 3][r] = bv.w;
        }
        __syncthreads();
#pragma unroll
        for (int k = 0; k < 16; k++) {
            float a[8], b[8];
            *reinterpret_cast<float4*>(a)     = *reinterpret_cast<const float4*>(&As[k][ty * 8]);
            *reinterpret_cast<float4*>(a + 4) = *reinterpret_cast<const float4*>(&As[k][ty * 8 + 4]);
            *reinterpret_cast<float4*>(b)     = *reinterpret_cast<const float4*>(&Bs[k][tx * 8]);
            *reinterpret_cast<float4*>(b + 4) = *reinterpret_cast<const float4*>(&Bs[k][tx * 8 + 4]);
#pragma unroll
            for (int i = 0; i < 8; i++)
#pragma unroll
                for (int j = 0; j < 8; j++) acc[i][j] = fmaf(a[i], b[j], acc[i][j]);
        }
        __syncthreads();
    }
    const int row = row0 + ty * 8;
    const int col = col0 + tx * 8;
    float bcol[8];
#pragma unroll
    for (int j = 0; j < 8; j++) bcol[j] = bias[col + j];
#pragma unroll
    for (int i = 0; i < 8; i++) {
        int r = row + i;
        float mr = (EPI >= 2) ? mask[r] : 1.f;
        float o[8];
#pragma unroll
        for (int j = 0; j < 8; j++) {
            float vv;
            if (EPI == 0)      vv = acc[i][j] + bcol[j];
            else if (EPI == 1) vv = (acc[i][j] + bcol[j]) * alpha;
            else if (EPI == 2) { vv = fmaf(acc[i][j], mr, bcol[j]); vv = fmaxf(vv, 0.f) * mr; }
            else               vv = (acc[i][j] + bcol[j]) * mr;
            o[j] = vv;
        }
        *reinterpret_cast<float4*>(&out[(long)r * N + col])     = *reinterpret_cast<float4*>(o);
        *reinterpret_cast<float4*>(&out[(long)r * N + col + 4]) = *reinterpret_cast<float4*>(o + 4);
    }
}

// ---------------- fused flash attention with windowed rel pos --------------
// q,k,v,ao layout: [B, L, C] with C = H*D (head slice contiguous).
// grid: (L/64, H, B), 256 threads (16x16 -> 4x4 micro-tiles).
#define ATTN_SMEM_FLOATS (3 * 64 * 68 + 64 * 12 + 576 + 576 + 64 + 64)
#define ATTN_SMEM_BYTES  (ATTN_SMEM_FLOATS * 4)

__global__ void __launch_bounds__(256) attn_kernel(
    const float* __restrict__ q, const float* __restrict__ k,
    const float* __restrict__ v, const float* __restrict__ relk,
    const float* __restrict__ relv, const float* __restrict__ mask,
    float* __restrict__ ao) {
    extern __shared__ float sm[];
    float* Qst = sm;                 // [64 d][68]: Qst[d*68 + r]
    float* KP  = Qst + 64 * 68;      // K: [d][m]  then P: [m][r]
    float* Vs  = KP  + 64 * 68;      // [m][d]: Vs[m*68 + d]
    float* rbs = Vs  + 64 * 68;      // [64 r][12]: q.rel_k dots
    float* rks = rbs + 64 * 12;      // [9][64]
    float* rvs = rks + 576;          // [9][64]
    float* mrow = rvs + 576;         // [64]
    float* mcol = mrow + 64;         // [64]

    const int tid = threadIdx.x;
    const int ty = tid >> 4, tx = tid & 15;
    const int b = blockIdx.z, h = blockIdx.y, l0 = blockIdx.x * 64;

    const float* qb = q + ((long)(b * Ln) + l0) * Cn + h * 64;
    for (int t = tid; t < 64 * 16; t += 256) {
        int r = t >> 4, d4 = (t & 15) << 2;
        float4 qv = *reinterpret_cast<const float4*>(&qb[(long)r * Cn + d4]);
        Qst[(d4 + 0) * 68 + r] = qv.x; Qst[(d4 + 1) * 68 + r] = qv.y;
        Qst[(d4 + 2) * 68 + r] = qv.z; Qst[(d4 + 3) * 68 + r] = qv.w;
    }
    for (int t = tid; t < 576; t += 256) { rks[t] = relk[t]; rvs[t] = relv[t]; }
    if (tid < 64) mrow[tid] = mask[b * Ln + l0 + tid];
    __syncthreads();

    // rb[r][j] = dot(q_row_r, rel_k[j])
    for (int t = tid; t < 64 * 9; t += 256) {
        int r = t / 9, j = t % 9;
        float s = 0.f;
#pragma unroll 8
        for (int d = 0; d < 64; d++) s = fmaf(Qst[d * 68 + r], rks[j * 64 + d], s);
        rbs[r * 12 + j] = s;
    }

    float m_old[4], ssum[4], acc[4][4];
#pragma unroll
    for (int i = 0; i < 4; i++) {
        m_old[i] = -3.0e38f; ssum[i] = 0.f;
#pragma unroll
        for (int j = 0; j < 4; j++) acc[i][j] = 0.f;
    }
    // this sync also orders rbs writes before their reads below
    __syncthreads();

    for (int ct = 0; ct < Ln / 64; ct++) {
        const int m0 = ct * 64;
        const float* kb = k + ((long)(b * Ln) + m0) * Cn + h * 64;
        const float* vb = v + ((long)(b * Ln) + m0) * Cn + h * 64;
        for (int t = tid; t < 64 * 16; t += 256) {
            int r = t >> 4, d4 = (t & 15) << 2;
            float4 kv = *reinterpret_cast<const float4*>(&kb[(long)r * Cn + d4]);
            KP[(d4 + 0) * 68 + r] = kv.x; KP[(d4 + 1) * 68 + r] = kv.y;
            KP[(d4 + 2) * 68 + r] = kv.z; KP[(d4 + 3) * 68 + r] = kv.w;
            float4 vv = *reinterpret_cast<const float4*>(&vb[(long)r * Cn + d4]);
            *reinterpret_cast<float4*>(&Vs[r * 68 + d4]) = vv;
        }
        if (tid < 64) mcol[tid] = mask[b * Ln + m0 + tid];
        __syncthreads();

        // S = Q K^T (64x64), 4x4 per thread
        float s[4][4];
#pragma unroll
        for (int i = 0; i < 4; i++)
#pragma unroll
            for (int j = 0; j < 4; j++) s[i][j] = 0.f;
#pragma unroll 16
        for (int d = 0; d < 64; d++) {
            float a[4], bb[4];
            *reinterpret_cast<float4*>(a)  = *reinterpret_cast<const float4*>(&Qst[d * 68 + 4 * ty]);
            *reinterpret_cast<float4*>(bb) = *reinterpret_cast<const float4*>(&KP[d * 68 + 4 * tx]);
#pragma unroll
            for (int i = 0; i < 4; i++)
#pragma unroll
                for (int j = 0; j < 4; j++) s[i][j] = fmaf(a[i], bb[j], s[i][j]);
        }
        // windowed rel_k bias + mask
#pragma unroll
        for (int i = 0; i < 4; i++) {
            int l = l0 + 4 * ty + i;
            float mr = mrow[4 * ty + i];
#pragma unroll
            for (int j = 0; j < 4; j++) {
                int m = m0 + 4 * tx + j;
                int diff = m - l;
                if (diff >= -Wn && diff <= Wn) s[i][j] += rbs[(4 * ty + i) * 12 + diff + Wn];
                if (mr * mcol[4 * tx + j] == 0.f) s[i][j] = -1e4f;
            }
        }
        // online softmax (row groups = 16 lanes sharing ty)
#pragma unroll
        for (int i = 0; i < 4; i++) {
            float mx = fmaxf(fmaxf(s[i][0], s[i][1]), fmaxf(s[i][2], s[i][3]));
#pragma unroll
            for (int off = 1; off < 16; off <<= 1)
                mx = fmaxf(mx, __shfl_xor_sync(0xffffffffu, mx, off));
            float mn = fmaxf(m_old[i], mx);
            float sc = __expf(m_old[i] - mn);
            m_old[i] = mn;
            float rs = 0.f;
#pragma unroll
            for (int j = 0; j < 4; j++) { s[i][j] = __expf(s[i][j] - mn); rs += s[i][j]; }
#pragma unroll
            for (int off = 1; off < 16; off <<= 1)
                rs += __shfl_xor_sync(0xffffffffu, rs, off);
            ssum[i] = ssum[i] * sc + rs;
#pragma unroll
            for (int j = 0; j < 4; j++) acc[i][j] *= sc;
        }
        __syncthreads();   // all K reads done -> reuse KP as P
#pragma unroll
        for (int i = 0; i < 4; i++)
#pragma unroll
            for (int j = 0; j < 4; j++)
                KP[(4 * tx + j) * 68 + 4 * ty + i] = s[i][j];   // Pst[m][r]
        __syncthreads();

        // O += P V
#pragma unroll 16
        for (int m = 0; m < 64; m++) {
            float p[4], vv[4];
            *reinterpret_cast<float4*>(p)  = *reinterpret_cast<const float4*>(&KP[m * 68 + 4 * ty]);
            *reinterpret_cast<float4*>(vv) = *reinterpret_cast<const float4*>(&Vs[m * 68 + 4 * tx]);
#pragma unroll
            for (int i = 0; i < 4; i++)
#pragma unroll
                for (int j = 0; j < 4; j++) acc[i][j] = fmaf(p[i], vv[j], acc[i][j]);
        }
        // O += P * rel_v (windowed)
#pragma unroll
        for (int i = 0; i < 4; i++) {
            int l = l0 + 4 * ty + i;
#pragma unroll
            for (int j = 0; j < 9; j++) {
                int m = l + j - Wn;
                if (m >= m0 && m < m0 + 64) {
                    float p = KP[(m - m0) * 68 + 4 * ty + i];
                    float rv[4];
                    *reinterpret_cast<float4*>(rv) =
                        *reinterpret_cast<const float4*>(&rvs[j * 64 + 4 * tx]);
#pragma unroll
                    for (int jd = 0; jd < 4; jd++) acc[i][jd] = fmaf(p, rv[jd], acc[i][jd]);
                }
            }
        }
        __syncthreads();   // P/V reads done before next tile's loads
    }
    // write output
#pragma unroll
    for (int i = 0; i < 4; i++) {
        int l = l0 + 4 * ty + i;
        float inv = 1.f / ssum[i];
        float o[4];
#pragma unroll
        for (int j = 0; j < 4; j++) o[j] = acc[i][j] * inv;
        *reinterpret_cast<float4*>(&ao[((long)(b * Ln) + l) * Cn + h * 64 + 4 * tx]) =
            *reinterpret_cast<float4*>(o);
    }
}

// ---------------- fused residual-add + LayerNorm over C --------------------
// out[row] = LN(res[row] + delta[row]) ; in-place (out==res) is safe per-block.
__global__ void __launch_bounds__(128) ln_kernel(
    const float* __restrict__ res, const float* __restrict__ delta,
    const float* __restrict__ g, const float* __restrict__ bta,
    float* __restrict__ out) {
    const int row = blockIdx.x;
    const int t = threadIdx.x;
    const float* rp = res + (long)row * Cn;
    const float* dp = delta + (long)row * Cn;
    float y[4];
    float s = 0.f, s2 = 0.f;
#pragma unroll
    for (int i = 0; i < 4; i++) {
        int c = t + i * 128;
        y[i] = rp[c] + dp[c];
        s += y[i]; s2 = fmaf(y[i], y[i], s2);
    }
#pragma unroll
    for (int off = 16; off > 0; off >>= 1) {
        s  += __shfl_xor_sync(0xffffffffu, s, off);
        s2 += __shfl_xor_sync(0xffffffffu, s2, off);
    }
    __shared__ float shs[4], shs2[4];
    int w = t >> 5;
    if ((t & 31) == 0) { shs[w] = s; shs2[w] = s2; }
    __syncthreads();
    float ts  = shs[0] + shs[1] + shs[2] + shs[3];
    float ts2 = shs2[0] + shs2[1] + shs2[2] + shs2[3];
    const float rn = 1.f / (float)Cn;
    float mu  = ts * rn;
    float var = ts2 * rn - mu * mu;
    float inv = rsqrtf(var + EPSF);
#pragma unroll
    for (int i = 0; i < 4; i++) {
        int c = t + i * 128;
        out[(long)row * Cn + c] = (y[i] - mu) * inv * g[c] + bta[c];
    }
}

// ---------------- launch ---------------------------------------------------
extern "C" void kernel_launch(void* const* d_in, const int* in_sizes, int n_in,
                              void* d_out, int out_size) {
    const float* x    = (const float*)d_in[0];
    const float* mask = (const float*)d_in[1];
    const float* wq   = (const float*)d_in[2];
    const float* bq   = (const float*)d_in[3];
    const float* wk   = (const float*)d_in[4];
    const float* bk   = (const float*)d_in[5];
    const float* wv   = (const float*)d_in[6];
    const float* bv   = (const float*)d_in[7];
    const float* wo   = (const float*)d_in[8];
    const float* bo   = (const float*)d_in[9];
    const float* relk = (const float*)d_in[10];
    const float* relv = (const float*)d_in[11];
    const float* ln1g = (const float*)d_in[12];
    const float* ln1b = (const float*)d_in[13];
    const float* w1   = (const float*)d_in[14];
    const float* b1   = (const float*)d_in[15];
    const float* w2   = (const float*)d_in[16];
    const float* b2   = (const float*)d_in[17];
    const float* ln2g = (const float*)d_in[18];
    const float* ln2b = (const float*)d_in[19];
    float* out = (float*)d_out;

    float *xt, *q, *k, *v, *ao, *tmp, *h;
    cudaGetSymbolAddress((void**)&xt,  g_xt);
    cudaGetSymbolAddress((void**)&q,   g_q);
    cudaGetSymbolAddress((void**)&k,   g_k);
    cudaGetSymbolAddress((void**)&v,   g_v);
    cudaGetSymbolAddress((void**)&ao,  g_ao);
    cudaGetSymbolAddress((void**)&tmp, g_tmp);
    cudaGetSymbolAddress((void**)&h,   g_h);

    cudaFuncSetAttribute((const void*)attn_kernel,
                         cudaFuncAttributeMaxDynamicSharedMemorySize, ATTN_SMEM_BYTES);

    transpose_in<<<dim3(Ln / 32, Cn / 32, Bn), dim3(32, 8)>>>(x, mask, xt);

    const dim3 gemmC(Cn / 128, Mrows / 128);    // N=512
    const dim3 gemmF(FCn / 128, Mrows / 128);   // N=2048

    for (int i = 0; i < NLn; i++) {
        const float* Wq = wq + (long)i * Cn * Cn;
        const float* Wk = wk + (long)i * Cn * Cn;
        const float* Wv = wv + (long)i * Cn * Cn;
        const float* Wo = wo + (long)i * Cn * Cn;
        const float* W1 = w1 + (long)i * FCn * Cn;
        const float* W2 = w2 + (long)i * Cn * FCn;

        sgemm_nt<1><<<gemmC, 256>>>(xt, Wq, bq + i * Cn, nullptr, q, Cn, Cn, SCALEF);
        sgemm_nt<0><<<gemmC, 256>>>(xt, Wk, bk + i * Cn, nullptr, k, Cn, Cn, 1.f);
        sgemm_nt<0><<<gemmC, 256>>>(xt, Wv, bv + i * Cn, nullptr, v, Cn, Cn, 1.f);

        attn_kernel<<<dim3(Ln / 64, Hn, Bn), 256, ATTN_SMEM_BYTES>>>(
            q, k, v, relk + i * 9 * Dn, relv + i * 9 * Dn, mask, ao);

        sgemm_nt<0><<<gemmC, 256>>>(ao, Wo, bo + i * Cn, nullptr, tmp, Cn, Cn, 1.f);
        ln_kernel<<<Mrows, 128>>>(xt, tmp, ln1g + i * Cn, ln1b + i * Cn, xt);

        sgemm_nt<2><<<gemmF, 256>>>(xt, W1, b1 + i * FCn, mask, h, FCn, Cn, 1.f);
        sgemm_nt<3><<<gemmC, 256>>>(h, W2, b2 + i * Cn, mask, tmp, Cn, FCn, 1.f);
        ln_kernel<<<Mrows, 128>>>(xt, tmp, ln2g + i * Cn, ln2b + i * Cn, xt);
    }

    transpose_out<<<dim3(Ln / 32, Cn / 32, Bn), dim3(32, 8)>>>(xt, mask, out);
}

// round 8
// speedup vs baseline: 1.7540x; 1.7540x over previous
#include <cuda_runtime.h>
#include <cstdint>

// Problem constants
#define Bn   4
#define Ln   1024
#define Cn   512
#define Hn   8
#define Dn   64
#define FCn  2048
#define NLn  4
#define Wn   4
#define Mrows (Bn * Ln)          // 4096
#define SCALEF 0.125f            // 64^-0.5
#define EPSF   1e-6f

// ---------------- scratch (static device memory; no allocations) -----------
__device__ float g_xt [Mrows * Cn];
__device__ float g_q  [Mrows * Cn];
__device__ float g_k  [Mrows * Cn];
__device__ float g_v  [Mrows * Cn];
__device__ float g_ao [Mrows * Cn];
__device__ float g_tmp[Mrows * Cn];
__device__ float g_h  [Mrows * FCn];

// ---------------- transpose in: x[B,C,L] -> xt[B,L,C], * mask --------------
__global__ void transpose_in(const float* __restrict__ x,
                             const float* __restrict__ mask,
                             float* __restrict__ xt) {
    __shared__ float tile[32][33];
    int b  = blockIdx.z;
    int c0 = blockIdx.y * 32, l0 = blockIdx.x * 32;
    int tx = threadIdx.x, ty = threadIdx.y;
    for (int i = ty; i < 32; i += 8)
        tile[i][tx] = x[((long)b * Cn + c0 + i) * Ln + l0 + tx];
    __syncthreads();
    for (int i = ty; i < 32; i += 8) {
        int l = l0 + i;
        xt[((long)b * Ln + l) * Cn + c0 + tx] = tile[tx][i] * mask[b * Ln + l];
    }
}

// ---------------- transpose out: xt[B,L,C] -> out[B,C,L], * mask -----------
__global__ void transpose_out(const float* __restrict__ xt,
                              const float* __restrict__ mask,
                              float* __restrict__ out) {
    __shared__ float tile[32][33];
    int b  = blockIdx.z;
    int c0 = blockIdx.y * 32, l0 = blockIdx.x * 32;
    int tx = threadIdx.x, ty = threadIdx.y;
    for (int i = ty; i < 32; i += 8)
        tile[i][tx] = xt[((long)b * Ln + l0 + i) * Cn + c0 + tx];
    __syncthreads();
    for (int i = ty; i < 32; i += 8)
        out[((long)b * Cn + c0 + i) * Ln + l0 + tx] = tile[tx][i] * mask[b * Ln + l0 + tx];
}

// ---------------- tf32 tensor-core GEMM NT ---------------------------------
// out[M,N] = A[M,K] @ Wt[N,K]^T  (+ epilogue), tf32 inputs / fp32 accum.
// Block tile 128x128, Ktile 32, 8 warps (2x4), warp tile 64x32, mma m16n8k8.
// EPI 0: out = acc + bias
// EPI 1: out = (acc + bias) * alpha
// EPI 2: out = relu(acc*mr + bias) * mr     (mr = mask[row])   [FFN1]
// EPI 3: out = (acc + bias) * mr                                [FFN2]

#define GEMM_LD   36                 // 32 + 4 pad (keeps float4 alignment)
#define GEMM_TILE (128 * GEMM_LD)    // floats per tile buffer
#define GEMM_SMEM_BYTES (4 * GEMM_TILE * 4)   // 2 bufs x (A+B)

__device__ __forceinline__ void sts_cvt_tf32(float* dst, float4 v) {
    uint32_t x, y, z, w;
    asm("cvt.rna.tf32.f32 %0, %1;" : "=r"(x) : "f"(v.x));
    asm("cvt.rna.tf32.f32 %0, %1;" : "=r"(y) : "f"(v.y));
    asm("cvt.rna.tf32.f32 %0, %1;" : "=r"(z) : "f"(v.z));
    asm("cvt.rna.tf32.f32 %0, %1;" : "=r"(w) : "f"(v.w));
    float4 o;
    o.x = __uint_as_float(x); o.y = __uint_as_float(y);
    o.z = __uint_as_float(z); o.w = __uint_as_float(w);
    *reinterpret_cast<float4*>(dst) = o;
}

__device__ __forceinline__ void mma_tf32(float* c, const uint32_t* a, const uint32_t* b) {
    asm volatile(
        "mma.sync.aligned.m16n8k8.row.col.f32.tf32.tf32.f32 "
        "{%0,%1,%2,%3}, {%4,%5,%6,%7}, {%8,%9}, {%0,%1,%2,%3};"
        : "+f"(c[0]), "+f"(c[1]), "+f"(c[2]), "+f"(c[3])
        : "r"(a[0]), "r"(a[1]), "r"(a[2]), "r"(a[3]), "r"(b[0]), "r"(b[1]));
}

template<int EPI>
__global__ void __launch_bounds__(256) gemm_tf32(
    const float* __restrict__ A, const float* __restrict__ Wt,
    const float* __restrict__ bias, const float* __restrict__ mask,
    float* __restrict__ out, int N, int K, float alpha) {
    extern __shared__ float sm[];
    float* Asm = sm;                    // 2 x GEMM_TILE
    float* Bsm = sm + 2 * GEMM_TILE;    // 2 x GEMM_TILE

    const int tid  = threadIdx.x;
    const int lane = tid & 31, warp = tid >> 5;
    const int wm = warp >> 2, wn = warp & 3;    // 2 x 4 warp grid
    const int g  = lane >> 2, t4 = lane & 3;
    const int row0 = blockIdx.y * 128, col0 = blockIdx.x * 128;
    const float* Ap = A  + (long)row0 * K;
    const float* Wp = Wt + (long)col0 * K;

    float acc[4][4][4];
#pragma unroll
    for (int mi = 0; mi < 4; mi++)
#pragma unroll
        for (int ni = 0; ni < 4; ni++)
#pragma unroll
            for (int e = 0; e < 4; e++) acc[mi][ni][e] = 0.f;

    // each thread loads 4 float4 of A and 4 of B per 128x32 tile
    int r_[4], kc_[4];
#pragma unroll
    for (int i = 0; i < 4; i++) {
        int idx = tid + i * 256;
        r_[i]  = idx >> 3;
        kc_[i] = (idx & 7) << 2;
    }

    float4 la[4], lb[4];
#pragma unroll
    for (int i = 0; i < 4; i++) {
        la[i] = *reinterpret_cast<const float4*>(&Ap[(long)r_[i] * K + kc_[i]]);
        lb[i] = *reinterpret_cast<const float4*>(&Wp[(long)r_[i] * K + kc_[i]]);
    }
#pragma unroll
    for (int i = 0; i < 4; i++) {
        sts_cvt_tf32(&Asm[r_[i] * GEMM_LD + kc_[i]], la[i]);
        sts_cvt_tf32(&Bsm[r_[i] * GEMM_LD + kc_[i]], lb[i]);
    }
    __syncthreads();

    const int ntiles = K >> 5;
    for (int kt = 0; kt < ntiles; kt++) {
        const int buf = kt & 1;
        if (kt + 1 < ntiles) {
            const int ko = (kt + 1) << 5;
#pragma unroll
            for (int i = 0; i < 4; i++) {
                la[i] = *reinterpret_cast<const float4*>(&Ap[(long)r_[i] * K + ko + kc_[i]]);
                lb[i] = *reinterpret_cast<const float4*>(&Wp[(long)r_[i] * K + ko + kc_[i]]);
            }
        }
        const float* Ab = Asm + buf * GEMM_TILE;
        const float* Bb = Bsm + buf * GEMM_TILE;
#pragma unroll
        for (int kk = 0; kk < 32; kk += 8) {
            uint32_t af[4][4], bf[4][2];
#pragma unroll
            for (int mi = 0; mi < 4; mi++) {
                int ar = (wm * 64 + mi * 16 + g) * GEMM_LD + kk + t4;
                af[mi][0] = __float_as_uint(Ab[ar]);
                af[mi][1] = __float_as_uint(Ab[ar + 8 * GEMM_LD]);
                af[mi][2] = __float_as_uint(Ab[ar + 4]);
                af[mi][3] = __float_as_uint(Ab[ar + 8 * GEMM_LD + 4]);
            }
#pragma unroll
            for (int ni = 0; ni < 4; ni++) {
                int br = (wn * 32 + ni * 8 + g) * GEMM_LD + kk + t4;
                bf[ni][0] = __float_as_uint(Bb[br]);
                bf[ni][1] = __float_as_uint(Bb[br + 4]);
            }
#pragma unroll
            for (int mi = 0; mi < 4; mi++)
#pragma unroll
                for (int ni = 0; ni < 4; ni++)
                    mma_tf32(acc[mi][ni], af[mi], bf[ni]);
        }
        if (kt + 1 < ntiles) {
            const int nb = (kt + 1) & 1;
#pragma unroll
            for (int i = 0; i < 4; i++) {
                sts_cvt_tf32(&Asm[nb * GEMM_TILE + r_[i] * GEMM_LD + kc_[i]], la[i]);
                sts_cvt_tf32(&Bsm[nb * GEMM_TILE + r_[i] * GEMM_LD + kc_[i]], lb[i]);
            }
        }
        __syncthreads();
    }

    // epilogue
#pragma unroll
    for (int mi = 0; mi < 4; mi++) {
        const int r0v = row0 + wm * 64 + mi * 16 + g;
        const int r1v = r0v + 8;
        float mr0 = (EPI >= 2) ? mask[r0v] : 1.f;
        float mr1 = (EPI >= 2) ? mask[r1v] : 1.f;
#pragma unroll
        for (int ni = 0; ni < 4; ni++) {
            const int c = col0 + wn * 32 + ni * 8 + t4 * 2;
            const float b0 = bias[c], b1 = bias[c + 1];
            float e00, e01, e10, e11;
            if (EPI == 0) {
                e00 = acc[mi][ni][0] + b0; e01 = acc[mi][ni][1] + b1;
                e10 = acc[mi][ni][2] + b0; e11 = acc[mi][ni][3] + b1;
            } else if (EPI == 1) {
                e00 = (acc[mi][ni][0] + b0) * alpha; e01 = (acc[mi][ni][1] + b1) * alpha;
                e10 = (acc[mi][ni][2] + b0) * alpha; e11 = (acc[mi][ni][3] + b1) * alpha;
            } else if (EPI == 2) {
                e00 = fmaxf(fmaf(acc[mi][ni][0], mr0, b0), 0.f) * mr0;
                e01 = fmaxf(fmaf(acc[mi][ni][1], mr0, b1), 0.f) * mr0;
                e10 = fmaxf(fmaf(acc[mi][ni][2], mr1, b0), 0.f) * mr1;
                e11 = fmaxf(fmaf(acc[mi][ni][3], mr1, b1), 0.f) * mr1;
            } else {
                e00 = (acc[mi][ni][0] + b0) * mr0; e01 = (acc[mi][ni][1] + b1) * mr0;
                e10 = (acc[mi][ni][2] + b0) * mr1; e11 = (acc[mi][ni][3] + b1) * mr1;
            }
            float2 o0 = make_float2(e00, e01);
            float2 o1 = make_float2(e10, e11);
            *reinterpret_cast<float2*>(&out[(long)r0v * N + c]) = o0;
            *reinterpret_cast<float2*>(&out[(long)r1v * N + c]) = o1;
        }
    }
}

// ---------------- fused flash attention with windowed rel pos --------------
// q,k,v,ao layout: [B, L, C] with C = H*D (head slice contiguous).
// grid: (L/64, H, B), 256 threads (16x16 -> 4x4 micro-tiles).
#define ATTN_SMEM_FLOATS (3 * 64 * 68 + 64 * 12 + 576 + 576 + 64 + 64)
#define ATTN_SMEM_BYTES  (ATTN_SMEM_FLOATS * 4)

__global__ void __launch_bounds__(256) attn_kernel(
    const float* __restrict__ q, const float* __restrict__ k,
    const float* __restrict__ v, const float* __restrict__ relk,
    const float* __restrict__ relv, const float* __restrict__ mask,
    float* __restrict__ ao) {
    extern __shared__ float sm[];
    float* Qst = sm;                 // [64 d][68]: Qst[d*68 + r]
    float* KP  = Qst + 64 * 68;      // K: [d][m]  then P: [m][r]
    float* Vs  = KP  + 64 * 68;      // [m][d]: Vs[m*68 + d]
    float* rbs = Vs  + 64 * 68;      // [64 r][12]: q.rel_k dots
    float* rks = rbs + 64 * 12;      // [9][64]
    float* rvs = rks + 576;          // [9][64]
    float* mrow = rvs + 576;         // [64]
    float* mcol = mrow + 64;         // [64]

    const int tid = threadIdx.x;
    const int ty = tid >> 4, tx = tid & 15;
    const int b = blockIdx.z, h = blockIdx.y, l0 = blockIdx.x * 64;

    const float* qb = q + ((long)(b * Ln) + l0) * Cn + h * 64;
    for (int t = tid; t < 64 * 16; t += 256) {
        int r = t >> 4, d4 = (t & 15) << 2;
        float4 qv = *reinterpret_cast<const float4*>(&qb[(long)r * Cn + d4]);
        Qst[(d4 + 0) * 68 + r] = qv.x; Qst[(d4 + 1) * 68 + r] = qv.y;
        Qst[(d4 + 2) * 68 + r] = qv.z; Qst[(d4 + 3) * 68 + r] = qv.w;
    }
    for (int t = tid; t < 576; t += 256) { rks[t] = relk[t]; rvs[t] = relv[t]; }
    if (tid < 64) mrow[tid] = mask[b * Ln + l0 + tid];
    __syncthreads();

    // rb[r][j] = dot(q_row_r, rel_k[j])
    for (int t = tid; t < 64 * 9; t += 256) {
        int r = t / 9, j = t % 9;
        float s = 0.f;
#pragma unroll 8
        for (int d = 0; d < 64; d++) s = fmaf(Qst[d * 68 + r], rks[j * 64 + d], s);
        rbs[r * 12 + j] = s;
    }

    float m_old[4], ssum[4], acc[4][4];
#pragma unroll
    for (int i = 0; i < 4; i++) {
        m_old[i] = -3.0e38f; ssum[i] = 0.f;
#pragma unroll
        for (int j = 0; j < 4; j++) acc[i][j] = 0.f;
    }
    // this sync also orders rbs writes before their reads below
    __syncthreads();

    for (int ct = 0; ct < Ln / 64; ct++) {
        const int m0 = ct * 64;
        const float* kb = k + ((long)(b * Ln) + m0) * Cn + h * 64;
        const float* vb = v + ((long)(b * Ln) + m0) * Cn + h * 64;
        for (int t = tid; t < 64 * 16; t += 256) {
            int r = t >> 4, d4 = (t & 15) << 2;
            float4 kv = *reinterpret_cast<const float4*>(&kb[(long)r * Cn + d4]);
            KP[(d4 + 0) * 68 + r] = kv.x; KP[(d4 + 1) * 68 + r] = kv.y;
            KP[(d4 + 2) * 68 + r] = kv.z; KP[(d4 + 3) * 68 + r] = kv.w;
            float4 vv = *reinterpret_cast<const float4*>(&vb[(long)r * Cn + d4]);
            *reinterpret_cast<float4*>(&Vs[r * 68 + d4]) = vv;
        }
        if (tid < 64) mcol[tid] = mask[b * Ln + m0 + tid];
        __syncthreads();

        // S = Q K^T (64x64), 4x4 per thread
        float s[4][4];
#pragma unroll
        for (int i = 0; i < 4; i++)
#pragma unroll
            for (int j = 0; j < 4; j++) s[i][j] = 0.f;
#pragma unroll 16
        for (int d = 0; d < 64; d++) {
            float a[4], bb[4];
            *reinterpret_cast<float4*>(a)  = *reinterpret_cast<const float4*>(&Qst[d * 68 + 4 * ty]);
            *reinterpret_cast<float4*>(bb) = *reinterpret_cast<const float4*>(&KP[d * 68 + 4 * tx]);
#pragma unroll
            for (int i = 0; i < 4; i++)
#pragma unroll
                for (int j = 0; j < 4; j++) s[i][j] = fmaf(a[i], bb[j], s[i][j]);
        }
        // windowed rel_k bias + mask
#pragma unroll
        for (int i = 0; i < 4; i++) {
            int l = l0 + 4 * ty + i;
            float mr = mrow[4 * ty + i];
#pragma unroll
            for (int j = 0; j < 4; j++) {
                int m = m0 + 4 * tx + j;
                int diff = m - l;
                if (diff >= -Wn && diff <= Wn) s[i][j] += rbs[(4 * ty + i) * 12 + diff + Wn];
                if (mr * mcol[4 * tx + j] == 0.f) s[i][j] = -1e4f;
            }
        }
        // online softmax (row groups = 16 lanes sharing ty)
#pragma unroll
        for (int i = 0; i < 4; i++) {
            float mx = fmaxf(fmaxf(s[i][0], s[i][1]), fmaxf(s[i][2], s[i][3]));
#pragma unroll
            for (int off = 1; off < 16; off <<= 1)
                mx = fmaxf(mx, __shfl_xor_sync(0xffffffffu, mx, off));
            float mn = fmaxf(m_old[i], mx);
            float sc = __expf(m_old[i] - mn);
            m_old[i] = mn;
            float rs = 0.f;
#pragma unroll
            for (int j = 0; j < 4; j++) { s[i][j] = __expf(s[i][j] - mn); rs += s[i][j]; }
#pragma unroll
            for (int off = 1; off < 16; off <<= 1)
                rs += __shfl_xor_sync(0xffffffffu, rs, off);
            ssum[i] = ssum[i] * sc + rs;
#pragma unroll
            for (int j = 0; j < 4; j++) acc[i][j] *= sc;
        }
        __syncthreads();   // all K reads done -> reuse KP as P
#pragma unroll
        for (int i = 0; i < 4; i++)
#pragma unroll
            for (int j = 0; j < 4; j++)
                KP[(4 * tx + j) * 68 + 4 * ty + i] = s[i][j];   // Pst[m][r]
        __syncthreads();

        // O += P V
#pragma unroll 16
        for (int m = 0; m < 64; m++) {
            float p[4], vv[4];
            *reinterpret_cast<float4*>(p)  = *reinterpret_cast<const float4*>(&KP[m * 68 + 4 * ty]);
            *reinterpret_cast<float4*>(vv) = *reinterpret_cast<const float4*>(&Vs[m * 68 + 4 * tx]);
#pragma unroll
            for (int i = 0; i < 4; i++)
#pragma unroll
                for (int j = 0; j < 4; j++) acc[i][j] = fmaf(p[i], vv[j], acc[i][j]);
        }
        // O += P * rel_v (windowed)
#pragma unroll
        for (int i = 0; i < 4; i++) {
            int l = l0 + 4 * ty + i;
#pragma unroll
            for (int j = 0; j < 9; j++) {
                int m = l + j - Wn;
                if (m >= m0 && m < m0 + 64) {
                    float p = KP[(m - m0) * 68 + 4 * ty + i];
                    float rv[4];
                    *reinterpret_cast<float4*>(rv) =
                        *reinterpret_cast<const float4*>(&rvs[j * 64 + 4 * tx]);
#pragma unroll
                    for (int jd = 0; jd < 4; jd++) acc[i][jd] = fmaf(p, rv[jd], acc[i][jd]);
                }
            }
        }
        __syncthreads();   // P/V reads done before next tile's loads
    }
    // write output
#pragma unroll
    for (int i = 0; i < 4; i++) {
        int l = l0 + 4 * ty + i;
        float inv = 1.f / ssum[i];
        float o[4];
#pragma unroll
        for (int j = 0; j < 4; j++) o[j] = acc[i][j] * inv;
        *reinterpret_cast<float4*>(&ao[((long)(b * Ln) + l) * Cn + h * 64 + 4 * tx]) =
            *reinterpret_cast<float4*>(o);
    }
}

// ---------------- fused residual-add + LayerNorm over C --------------------
__global__ void __launch_bounds__(128) ln_kernel(
    const float* __restrict__ res, const float* __restrict__ delta,
    const float* __restrict__ g, const float* __restrict__ bta,
    float* __restrict__ out) {
    const int row = blockIdx.x;
    const int t = threadIdx.x;
    const float* rp = res + (long)row * Cn;
    const float* dp = delta + (long)row * Cn;
    float y[4];
    float s = 0.f, s2 = 0.f;
#pragma unroll
    for (int i = 0; i < 4; i++) {
        int c = t + i * 128;
        y[i] = rp[c] + dp[c];
        s += y[i]; s2 = fmaf(y[i], y[i], s2);
    }
#pragma unroll
    for (int off = 16; off > 0; off >>= 1) {
        s  += __shfl_xor_sync(0xffffffffu, s, off);
        s2 += __shfl_xor_sync(0xffffffffu, s2, off);
    }
    __shared__ float shs[4], shs2[4];
    int w = t >> 5;
    if ((t & 31) == 0) { shs[w] = s; shs2[w] = s2; }
    __syncthreads();
    float ts  = shs[0] + shs[1] + shs[2] + shs[3];
    float ts2 = shs2[0] + shs2[1] + shs2[2] + shs2[3];
    const float rn = 1.f / (float)Cn;
    float mu  = ts * rn;
    float var = ts2 * rn - mu * mu;
    float inv = rsqrtf(var + EPSF);
#pragma unroll
    for (int i = 0; i < 4; i++) {
        int c = t + i * 128;
        out[(long)row * Cn + c] = (y[i] - mu) * inv * g[c] + bta[c];
    }
}

// ---------------- launch ---------------------------------------------------
extern "C" void kernel_launch(void* const* d_in, const int* in_sizes, int n_in,
                              void* d_out, int out_size) {
    const float* x    = (const float*)d_in[0];
    const float* mask = (const float*)d_in[1];
    const float* wq   = (const float*)d_in[2];
    const float* bq   = (const float*)d_in[3];
    const float* wk   = (const float*)d_in[4];
    const float* bk   = (const float*)d_in[5];
    const float* wv   = (const float*)d_in[6];
    const float* bv   = (const float*)d_in[7];
    const float* wo   = (const float*)d_in[8];
    const float* bo   = (const float*)d_in[9];
    const float* relk = (const float*)d_in[10];
    const float* relv = (const float*)d_in[11];
    const float* ln1g = (const float*)d_in[12];
    const float* ln1b = (const float*)d_in[13];
    const float* w1   = (const float*)d_in[14];
    const float* b1   = (const float*)d_in[15];
    const float* w2   = (const float*)d_in[16];
    const float* b2   = (const float*)d_in[17];
    const float* ln2g = (const float*)d_in[18];
    const float* ln2b = (const float*)d_in[19];
    float* out = (float*)d_out;

    float *xt, *q, *k, *v, *ao, *tmp, *h;
    cudaGetSymbolAddress((void**)&xt,  g_xt);
    cudaGetSymbolAddress((void**)&q,   g_q);
    cudaGetSymbolAddress((void**)&k,   g_k);
    cudaGetSymbolAddress((void**)&v,   g_v);
    cudaGetSymbolAddress((void**)&ao,  g_ao);
    cudaGetSymbolAddress((void**)&tmp, g_tmp);
    cudaGetSymbolAddress((void**)&h,   g_h);

    cudaFuncSetAttribute((const void*)attn_kernel,
                         cudaFuncAttributeMaxDynamicSharedMemorySize, ATTN_SMEM_BYTES);
    cudaFuncSetAttribute((const void*)gemm_tf32<0>,
                         cudaFuncAttributeMaxDynamicSharedMemorySize, GEMM_SMEM_BYTES);
    cudaFuncSetAttribute((const void*)gemm_tf32<1>,
                         cudaFuncAttributeMaxDynamicSharedMemorySize, GEMM_SMEM_BYTES);
    cudaFuncSetAttribute((const void*)gemm_tf32<2>,
                         cudaFuncAttributeMaxDynamicSharedMemorySize, GEMM_SMEM_BYTES);
    cudaFuncSetAttribute((const void*)gemm_tf32<3>,
                         cudaFuncAttributeMaxDynamicSharedMemorySize, GEMM_SMEM_BYTES);

    transpose_in<<<dim3(Ln / 32, Cn / 32, Bn), dim3(32, 8)>>>(x, mask, xt);

    const dim3 gemmC(Cn / 128, Mrows / 128);    // N=512
    const dim3 gemmF(FCn / 128, Mrows / 128);   // N=2048

    for (int i = 0; i < NLn; i++) {
        const float* Wq = wq + (long)i * Cn * Cn;
        const float* Wk = wk + (long)i * Cn * Cn;
        const float* Wv = wv + (long)i * Cn * Cn;
        const float* Wo = wo + (long)i * Cn * Cn;
        const float* W1 = w1 + (long)i * FCn * Cn;
        const float* W2 = w2 + (long)i * Cn * FCn;

        gemm_tf32<1><<<gemmC, 256, GEMM_SMEM_BYTES>>>(xt, Wq, bq + i * Cn, nullptr, q, Cn, Cn, SCALEF);
        gemm_tf32<0><<<gemmC, 256, GEMM_SMEM_BYTES>>>(xt, Wk, bk + i * Cn, nullptr, k, Cn, Cn, 1.f);
        gemm_tf32<0><<<gemmC, 256, GEMM_SMEM_BYTES>>>(xt, Wv, bv + i * Cn, nullptr, v, Cn, Cn, 1.f);

        attn_kernel<<<dim3(Ln / 64, Hn, Bn), 256, ATTN_SMEM_BYTES>>>(
            q, k, v, relk + i * 9 * Dn, relv + i * 9 * Dn, mask, ao);

        gemm_tf32<0><<<gemmC, 256, GEMM_SMEM_BYTES>>>(ao, Wo, bo + i * Cn, nullptr, tmp, Cn, Cn, 1.f);
        ln_kernel<<<Mrows, 128>>>(xt, tmp, ln1g + i * Cn, ln1b + i * Cn, xt);

        gemm_tf32<2><<<gemmF, 256, GEMM_SMEM_BYTES>>>(xt, W1, b1 + i * FCn, mask, h, FCn, Cn, 1.f);
        gemm_tf32<3><<<gemmC, 256, GEMM_SMEM_BYTES>>>(h, W2, b2 + i * Cn, mask, tmp, Cn, FCn, 1.f);
        ln_kernel<<<Mrows, 128>>>(xt, tmp, ln2g + i * Cn, ln2b + i * Cn, xt);
    }

    transpose_out<<<dim3(Ln / 32, Cn / 32, Bn), dim3(32, 8)>>>(xt, mask, out);
}

// round 12
// speedup vs baseline: 2.6121x; 1.4892x over previous
#include <cuda_runtime.h>
#include <cstdint>

// Problem constants
#define Bn   4
#define Ln   1024
#define Cn   512
#define Hn   8
#define Dn   64
#define FCn  2048
#define NLn  4
#define Wn   4
#define Mrows (Bn * Ln)          // 4096
#define SCALEF 0.125f            // 64^-0.5
#define EPSF   1e-6f

// ---------------- scratch (static device memory; no allocations) -----------
__device__ float g_xt [Mrows * Cn];
__device__ float g_q  [Mrows * Cn];
__device__ float g_k  [Mrows * Cn];
__device__ float g_v  [Mrows * Cn];
__device__ float g_ao [Mrows * Cn];
__device__ float g_tmp[Mrows * Cn];
__device__ float g_h  [Mrows * FCn];

// ---------------- tf32 helpers ---------------------------------------------
__device__ __forceinline__ void sts_cvt_tf32(float* dst, float4 v) {
    uint32_t x, y, z, w;
    asm("cvt.rna.tf32.f32 %0, %1;" : "=r"(x) : "f"(v.x));
    asm("cvt.rna.tf32.f32 %0, %1;" : "=r"(y) : "f"(v.y));
    asm("cvt.rna.tf32.f32 %0, %1;" : "=r"(z) : "f"(v.z));
    asm("cvt.rna.tf32.f32 %0, %1;" : "=r"(w) : "f"(v.w));
    float4 o;
    o.x = __uint_as_float(x); o.y = __uint_as_float(y);
    o.z = __uint_as_float(z); o.w = __uint_as_float(w);
    *reinterpret_cast<float4*>(dst) = o;
}

__device__ __forceinline__ float cvt1_tf32(float x) {
    uint32_t u;
    asm("cvt.rna.tf32.f32 %0, %1;" : "=r"(u) : "f"(x));
    return __uint_as_float(u);
}

__device__ __forceinline__ void mma_tf32(float* c, const uint32_t* a, const uint32_t* b) {
    asm volatile(
        "mma.sync.aligned.m16n8k8.row.col.f32.tf32.tf32.f32 "
        "{%0,%1,%2,%3}, {%4,%5,%6,%7}, {%8,%9}, {%0,%1,%2,%3};"
        : "+f"(c[0]), "+f"(c[1]), "+f"(c[2]), "+f"(c[3])
        : "r"(a[0]), "r"(a[1]), "r"(a[2]), "r"(a[3]), "r"(b[0]), "r"(b[1]));
}

// ---------------- transpose in: x[B,C,L] -> xt[B,L,C], * mask --------------
__global__ void transpose_in(const float* __restrict__ x,
                             const float* __restrict__ mask,
                             float* __restrict__ xt) {
    __shared__ float tile[32][33];
    int b  = blockIdx.z;
    int c0 = blockIdx.y * 32, l0 = blockIdx.x * 32;
    int tx = threadIdx.x, ty = threadIdx.y;
    for (int i = ty; i < 32; i += 8)
        tile[i][tx] = x[((long)b * Cn + c0 + i) * Ln + l0 + tx];
    __syncthreads();
    for (int i = ty; i < 32; i += 8) {
        int l = l0 + i;
        xt[((long)b * Ln + l) * Cn + c0 + tx] = tile[tx][i] * mask[b * Ln + l];
    }
}

// ---------------- transpose out: xt[B,L,C] -> out[B,C,L], * mask -----------
__global__ void transpose_out(const float* __restrict__ xt,
                              const float* __restrict__ mask,
                              float* __restrict__ out) {
    __shared__ float tile[32][33];
    int b  = blockIdx.z;
    int c0 = blockIdx.y * 32, l0 = blockIdx.x * 32;
    int tx = threadIdx.x, ty = threadIdx.y;
    for (int i = ty; i < 32; i += 8)
        tile[i][tx] = xt[((long)b * Ln + l0 + i) * Cn + c0 + tx];
    __syncthreads();
    for (int i = ty; i < 32; i += 8)
        out[((long)b * Cn + c0 + i) * Ln + l0 + tx] = tile[tx][i] * mask[b * Ln + l0 + tx];
}

// ---------------- tf32 tensor-core GEMM NT ---------------------------------
#define GEMM_LD   36
#define GEMM_TILE (128 * GEMM_LD)
#define GEMM_SMEM_BYTES (4 * GEMM_TILE * 4)

template<int EPI>
__global__ void __launch_bounds__(256) gemm_tf32(
    const float* __restrict__ A, const float* __restrict__ Wt,
    const float* __restrict__ bias, const float* __restrict__ mask,
    float* __restrict__ out, int N, int K, float alpha) {
    extern __shared__ float sm[];
    float* Asm = sm;
    float* Bsm = sm + 2 * GEMM_TILE;

    const int tid  = threadIdx.x;
    const int lane = tid & 31, warp = tid >> 5;
    const int wm = warp >> 2, wn = warp & 3;
    const int g  = lane >> 2, t4 = lane & 3;
    const int row0 = blockIdx.y * 128, col0 = blockIdx.x * 128;
    const float* Ap = A  + (long)row0 * K;
    const float* Wp = Wt + (long)col0 * K;

    float acc[4][4][4];
#pragma unroll
    for (int mi = 0; mi < 4; mi++)
#pragma unroll
        for (int ni = 0; ni < 4; ni++)
#pragma unroll
            for (int e = 0; e < 4; e++) acc[mi][ni][e] = 0.f;

    int r_[4], kc_[4];
#pragma unroll
    for (int i = 0; i < 4; i++) {
        int idx = tid + i * 256;
        r_[i]  = idx >> 3;
        kc_[i] = (idx & 7) << 2;
    }

    float4 la[4], lb[4];
#pragma unroll
    for (int i = 0; i < 4; i++) {
        la[i] = *reinterpret_cast<const float4*>(&Ap[(long)r_[i] * K + kc_[i]]);
        lb[i] = *reinterpret_cast<const float4*>(&Wp[(long)r_[i] * K + kc_[i]]);
    }
#pragma unroll
    for (int i = 0; i < 4; i++) {
        sts_cvt_tf32(&Asm[r_[i] * GEMM_LD + kc_[i]], la[i]);
        sts_cvt_tf32(&Bsm[r_[i] * GEMM_LD + kc_[i]], lb[i]);
    }
    __syncthreads();

    const int ntiles = K >> 5;
    for (int kt = 0; kt < ntiles; kt++) {
        const int buf = kt & 1;
        if (kt + 1 < ntiles) {
            const int ko = (kt + 1) << 5;
#pragma unroll
            for (int i = 0; i < 4; i++) {
                la[i] = *reinterpret_cast<const float4*>(&Ap[(long)r_[i] * K + ko + kc_[i]]);
                lb[i] = *reinterpret_cast<const float4*>(&Wp[(long)r_[i] * K + ko + kc_[i]]);
            }
        }
        const float* Ab = Asm + buf * GEMM_TILE;
        const float* Bb = Bsm + buf * GEMM_TILE;
#pragma unroll
        for (int kk = 0; kk < 32; kk += 8) {
            uint32_t af[4][4], bf[4][2];
#pragma unroll
            for (int mi = 0; mi < 4; mi++) {
                int ar = (wm * 64 + mi * 16 + g) * GEMM_LD + kk + t4;
                af[mi][0] = __float_as_uint(Ab[ar]);
                af[mi][1] = __float_as_uint(Ab[ar + 8 * GEMM_LD]);
                af[mi][2] = __float_as_uint(Ab[ar + 4]);
                af[mi][3] = __float_as_uint(Ab[ar + 8 * GEMM_LD + 4]);
            }
#pragma unroll
            for (int ni = 0; ni < 4; ni++) {
                int br = (wn * 32 + ni * 8 + g) * GEMM_LD + kk + t4;
                bf[ni][0] = __float_as_uint(Bb[br]);
                bf[ni][1] = __float_as_uint(Bb[br + 4]);
            }
#pragma unroll
            for (int mi = 0; mi < 4; mi++)
#pragma unroll
                for (int ni = 0; ni < 4; ni++)
                    mma_tf32(acc[mi][ni], af[mi], bf[ni]);
        }
        if (kt + 1 < ntiles) {
            const int nb = (kt + 1) & 1;
#pragma unroll
            for (int i = 0; i < 4; i++) {
                sts_cvt_tf32(&Asm[nb * GEMM_TILE + r_[i] * GEMM_LD + kc_[i]], la[i]);
                sts_cvt_tf32(&Bsm[nb * GEMM_TILE + r_[i] * GEMM_LD + kc_[i]], lb[i]);
            }
        }
        __syncthreads();
    }

#pragma unroll
    for (int mi = 0; mi < 4; mi++) {
        const int r0v = row0 + wm * 64 + mi * 16 + g;
        const int r1v = r0v + 8;
        float mr0 = (EPI >= 2) ? mask[r0v] : 1.f;
        float mr1 = (EPI >= 2) ? mask[r1v] : 1.f;
#pragma unroll
        for (int ni = 0; ni < 4; ni++) {
            const int c = col0 + wn * 32 + ni * 8 + t4 * 2;
            const float b0 = bias[c], b1 = bias[c + 1];
            float e00, e01, e10, e11;
            if (EPI == 0) {
                e00 = acc[mi][ni][0] + b0; e01 = acc[mi][ni][1] + b1;
                e10 = acc[mi][ni][2] + b0; e11 = acc[mi][ni][3] + b1;
            } else if (EPI == 1) {
                e00 = (acc[mi][ni][0] + b0) * alpha; e01 = (acc[mi][ni][1] + b1) * alpha;
                e10 = (acc[mi][ni][2] + b0) * alpha; e11 = (acc[mi][ni][3] + b1) * alpha;
            } else if (EPI == 2) {
                e00 = fmaxf(fmaf(acc[mi][ni][0], mr0, b0), 0.f) * mr0;
                e01 = fmaxf(fmaf(acc[mi][ni][1], mr0, b1), 0.f) * mr0;
                e10 = fmaxf(fmaf(acc[mi][ni][2], mr1, b0), 0.f) * mr1;
                e11 = fmaxf(fmaf(acc[mi][ni][3], mr1, b1), 0.f) * mr1;
            } else {
                e00 = (acc[mi][ni][0] + b0) * mr0; e01 = (acc[mi][ni][1] + b1) * mr0;
                e10 = (acc[mi][ni][2] + b0) * mr1; e11 = (acc[mi][ni][3] + b1) * mr1;
            }
            *reinterpret_cast<float2*>(&out[(long)r0v * N + c]) = make_float2(e00, e01);
            *reinterpret_cast<float2*>(&out[(long)r1v * N + c]) = make_float2(e10, e11);
        }
    }
}

// ---------------- tensor-core flash attention with windowed rel pos --------
// 128 Q-rows per block, 8 warps (16 rows each, full 64-col KV tile).
// tf32 MMA for S=QK^T and O+=PV; rel_v folded in after the loop via windowed
// probability accumulators w[row][9] maintained in smem with online rescale.
#define BQ 128
#define BK 64
#define QLD 68
#define VLD 72
#define OFF_QS   0
#define OFF_KS   (OFF_QS + BQ * QLD)
#define OFF_VS   (OFF_KS + BK * QLD)
#define OFF_PS   (OFF_VS + BK * VLD)
#define OFF_RBS  (OFF_PS + BQ * QLD)
#define OFF_RKS  (OFF_RBS + BQ * 12)
#define OFF_RVS  (OFF_RKS + 576)
#define OFF_WS   (OFF_RVS + 576)
#define OFF_SCS  (OFF_WS + BQ * 12)
#define OFF_MROW (OFF_SCS + BQ)
#define OFF_MCOL (OFF_MROW + BQ)
#define ATTN2_FLOATS (OFF_MCOL + BK)
#define ATTN2_SMEM_BYTES (ATTN2_FLOATS * 4)

__global__ void __launch_bounds__(256) attn_tc_kernel(
    const float* __restrict__ q, const float* __restrict__ k,
    const float* __restrict__ v, const float* __restrict__ relk,
    const float* __restrict__ relv, const float* __restrict__ mask,
    float* __restrict__ ao) {
    extern __shared__ float sm[];
    float* Qs   = sm + OFF_QS;
    float* Ks   = sm + OFF_KS;
    float* Vs   = sm + OFF_VS;
    float* Ps   = sm + OFF_PS;
    float* rbs  = sm + OFF_RBS;
    float* rks  = sm + OFF_RKS;
    float* rvs  = sm + OFF_RVS;
    float* ws   = sm + OFF_WS;
    float* scs  = sm + OFF_SCS;
    float* mrow = sm + OFF_MROW;
    float* mcol = sm + OFF_MCOL;

    const int tid  = threadIdx.x;
    const int lane = tid & 31, warp = tid >> 5;
    const int g = lane >> 2, t4 = lane & 3;
    const int qr0 = warp * 16;
    const int b = blockIdx.z, h = blockIdx.y, l0 = blockIdx.x * BQ;

    const int rl0 = qr0 + g, rl1 = rl0 + 8;
    const int lg0 = l0 + rl0, lg1 = l0 + rl1;

    // load Q (tf32), rel tables, row mask; zero w accumulators
    const float* qb = q + ((long)(b * Ln) + l0) * Cn + h * 64;
    for (int t = tid; t < BQ * 16; t += 256) {
        int r = t >> 4, d4 = (t & 15) << 2;
        float4 qv = *reinterpret_cast<const float4*>(&qb[(long)r * Cn + d4]);
        sts_cvt_tf32(&Qs[r * QLD + d4], qv);
    }
    for (int t = tid; t < 576; t += 256) { rks[t] = relk[t]; rvs[t] = relv[t]; }
    if (tid < BQ) mrow[tid] = mask[b * Ln + l0 + tid];
    for (int t = tid; t < BQ * 12; t += 256) ws[t] = 0.f;
    __syncthreads();

    // rbs[r][j] = dot(q_row_r, rel_k[j])   (uses tf32-rounded Q; fine)
    for (int t = tid; t < BQ * 9; t += 256) {
        int r = t / 9, j = t - r * 9;
        float s = 0.f;
#pragma unroll 8
        for (int d = 0; d < 64; d++) s = fmaf(Qs[r * QLD + d], rks[j * 64 + d], s);
        rbs[r * 12 + j] = s;
    }
    // rbs ready after the first tile's post-load sync

    float m0v0 = -3.0e38f, m0v1 = -3.0e38f;
    float ssum0 = 0.f, ssum1 = 0.f;
    float o[8][4];
#pragma unroll
    for (int ni = 0; ni < 8; ni++)
#pragma unroll
        for (int e = 0; e < 4; e++) o[ni][e] = 0.f;

    for (int ct = 0; ct < Ln / BK; ct++) {
        const int m0 = ct * BK;
        const float* kb = k + ((long)(b * Ln) + m0) * Cn + h * 64;
        const float* vb = v + ((long)(b * Ln) + m0) * Cn + h * 64;
        for (int t = tid; t < BK * 16; t += 256) {
            int r = t >> 4, d4 = (t & 15) << 2;
            float4 kv = *reinterpret_cast<const float4*>(&kb[(long)r * Cn + d4]);
            sts_cvt_tf32(&Ks[r * QLD + d4], kv);
            float4 vv = *reinterpret_cast<const float4*>(&vb[(long)r * Cn + d4]);
            sts_cvt_tf32(&Vs[r * VLD + d4], vv);
        }
        if (tid < BK) mcol[tid] = mask[b * Ln + m0 + tid];
        __syncthreads();

        // S = Q K^T : warp computes 16 x 64
        float s[8][4];
#pragma unroll
        for (int ni = 0; ni < 8; ni++)
#pragma unroll
            for (int e = 0; e < 4; e++) s[ni][e] = 0.f;
#pragma unroll
        for (int kk = 0; kk < 64; kk += 8) {
            uint32_t a[4];
            const int ar = rl0 * QLD + kk + t4;
            a[0] = __float_as_uint(Qs[ar]);
            a[1] = __float_as_uint(Qs[ar + 8 * QLD]);
            a[2] = __float_as_uint(Qs[ar + 4]);
            a[3] = __float_as_uint(Qs[ar + 8 * QLD + 4]);
#pragma unroll
            for (int ni = 0; ni < 8; ni++) {
                uint32_t bf[2];
                const int br = (ni * 8 + g) * QLD + kk + t4;
                bf[0] = __float_as_uint(Ks[br]);
                bf[1] = __float_as_uint(Ks[br + 4]);
                mma_tf32(s[ni], a, bf);
            }
        }

        // rel_k bias + mask
        const float mr0 = mrow[rl0], mr1 = mrow[rl1];
#pragma unroll
        for (int ni = 0; ni < 8; ni++)
#pragma unroll
            for (int e = 0; e < 2; e++) {
                const int mc = ni * 8 + 2 * t4 + e;
                const int mg = m0 + mc;
                const float mcv = mcol[mc];
                int d0 = mg - lg0;
                if (d0 >= -Wn && d0 <= Wn) s[ni][e] += rbs[rl0 * 12 + d0 + Wn];
                if (mr0 * mcv == 0.f) s[ni][e] = -1e4f;
                int d1 = mg - lg1;
                if (d1 >= -Wn && d1 <= Wn) s[ni][2 + e] += rbs[rl1 * 12 + d1 + Wn];
                if (mr1 * mcv == 0.f) s[ni][2 + e] = -1e4f;
            }

        // online softmax (rows rl0, rl1); row spans the quad (t4 lanes)
        float mx0 = -3.0e38f, mx1 = -3.0e38f;
#pragma unroll
        for (int ni = 0; ni < 8; ni++) {
            mx0 = fmaxf(mx0, fmaxf(s[ni][0], s[ni][1]));
            mx1 = fmaxf(mx1, fmaxf(s[ni][2], s[ni][3]));
        }
        mx0 = fmaxf(mx0, __shfl_xor_sync(0xffffffffu, mx0, 1));
        mx0 = fmaxf(mx0, __shfl_xor_sync(0xffffffffu, mx0, 2));
        mx1 = fmaxf(mx1, __shfl_xor_sync(0xffffffffu, mx1, 1));
        mx1 = fmaxf(mx1, __shfl_xor_sync(0xffffffffu, mx1, 2));
        const float mn0 = fmaxf(m0v0, mx0), mn1 = fmaxf(m0v1, mx1);
        const float sc0 = __expf(m0v0 - mn0), sc1 = __expf(m0v1 - mn1);
        m0v0 = mn0; m0v1 = mn1;
        float rs0 = 0.f, rs1 = 0.f;
#pragma unroll
        for (int ni = 0; ni < 8; ni++) {
            s[ni][0] = __expf(s[ni][0] - mn0); rs0 += s[ni][0];
            s[ni][1] = __expf(s[ni][1] - mn0); rs0 += s[ni][1];
            s[ni][2] = __expf(s[ni][2] - mn1); rs1 += s[ni][2];
            s[ni][3] = __expf(s[ni][3] - mn1); rs1 += s[ni][3];
        }
        rs0 += __shfl_xor_sync(0xffffffffu, rs0, 1);
        rs0 += __shfl_xor_sync(0xffffffffu, rs0, 2);
        rs1 += __shfl_xor_sync(0xffffffffu, rs1, 1);
        rs1 += __shfl_xor_sync(0xffffffffu, rs1, 2);
        ssum0 = ssum0 * sc0 + rs0;
        ssum1 = ssum1 * sc1 + rs1;
#pragma unroll
        for (int ni = 0; ni < 8; ni++) {
            o[ni][0] *= sc0; o[ni][1] *= sc0;
            o[ni][2] *= sc1; o[ni][3] *= sc1;
        }
        if (t4 == 0) { scs[rl0] = sc0; scs[rl1] = sc1; }

        // store P (tf32) for the PV mma + w gather
#pragma unroll
        for (int ni = 0; ni < 8; ni++)
#pragma unroll
            for (int e = 0; e < 2; e++) {
                const int mc = ni * 8 + 2 * t4 + e;
                Ps[rl0 * QLD + mc] = cvt1_tf32(s[ni][e]);
                Ps[rl1 * QLD + mc] = cvt1_tf32(s[ni][2 + e]);
            }
        __syncthreads();

        // windowed probability accumulators: w = w*sc + P[l][l+j-4] if in tile
        for (int t = tid; t < BQ * 9; t += 256) {
            int r = t / 9, j = t - r * 9;
            int m = l0 + r + j - Wn - m0;
            float add = (m >= 0 && m < BK) ? Ps[r * QLD + m] : 0.f;
            ws[r * 12 + j] = ws[r * 12 + j] * scs[r] + add;
        }

        // O += P V
#pragma unroll
        for (int kk = 0; kk < 64; kk += 8) {
            uint32_t a[4];
            const int ar = rl0 * QLD + kk + t4;
            a[0] = __float_as_uint(Ps[ar]);
            a[1] = __float_as_uint(Ps[ar + 8 * QLD]);
            a[2] = __float_as_uint(Ps[ar + 4]);
            a[3] = __float_as_uint(Ps[ar + 8 * QLD + 4]);
#pragma unroll
            for (int ni = 0; ni < 8; ni++) {
                uint32_t bf[2];
                const int br = (kk + t4) * VLD + ni * 8 + g;
                bf[0] = __float_as_uint(Vs[br]);
                bf[1] = __float_as_uint(Vs[br + 4 * VLD]);
                mma_tf32(o[ni], a, bf);
            }
        }
        __syncthreads();
    }

    // rel_v contribution + normalize + write
    float w0[9], w1[9];
#pragma unroll
    for (int j = 0; j < 9; j++) { w0[j] = ws[rl0 * 12 + j]; w1[j] = ws[rl1 * 12 + j]; }
    const float inv0 = 1.f / ssum0, inv1 = 1.f / ssum1;
    float* aob = ao + ((long)(b * Ln) + l0) * Cn + h * 64;
#pragma unroll
    for (int ni = 0; ni < 8; ni++) {
        const int mc0 = ni * 8 + 2 * t4;
        float r0a = o[ni][0], r0b = o[ni][1], r1a = o[ni][2], r1b = o[ni][3];
#pragma unroll
        for (int j = 0; j < 9; j++) {
            const float rva = rvs[j * 64 + mc0], rvb = rvs[j * 64 + mc0 + 1];
            r0a = fmaf(w0[j], rva, r0a); r0b = fmaf(w0[j], rvb, r0b);
            r1a = fmaf(w1[j], rva, r1a); r1b = fmaf(w1[j], rvb, r1b);
        }
        *reinterpret_cast<float2*>(&aob[(long)rl0 * Cn + mc0]) = make_float2(r0a * inv0, r0b * inv0);
        *reinterpret_cast<float2*>(&aob[(long)rl1 * Cn + mc0]) = make_float2(r1a * inv1, r1b * inv1);
    }
}

// ---------------- fused residual-add + LayerNorm over C --------------------
__global__ void __launch_bounds__(128) ln_kernel(
    const float* __restrict__ res, const float* __restrict__ delta,
    const float* __restrict__ g, const float* __restrict__ bta,
    float* __restrict__ out) {
    const int row = blockIdx.x;
    const int t = threadIdx.x;
    const float* rp = res + (long)row * Cn;
    const float* dp = delta + (long)row * Cn;
    float y[4];
    float s = 0.f, s2 = 0.f;
#pragma unroll
    for (int i = 0; i < 4; i++) {
        int c = t + i * 128;
        y[i] = rp[c] + dp[c];
        s += y[i]; s2 = fmaf(y[i], y[i], s2);
    }
#pragma unroll
    for (int off = 16; off > 0; off >>= 1) {
        s  += __shfl_xor_sync(0xffffffffu, s, off);
        s2 += __shfl_xor_sync(0xffffffffu, s2, off);
    }
    __shared__ float shs[4], shs2[4];
    int w = t >> 5;
    if ((t & 31) == 0) { shs[w] = s; shs2[w] = s2; }
    __syncthreads();
    float ts  = shs[0] + shs[1] + shs[2] + shs[3];
    float ts2 = shs2[0] + shs2[1] + shs2[2] + shs2[3];
    const float rn = 1.f / (float)Cn;
    float mu  = ts * rn;
    float var = ts2 * rn - mu * mu;
    float inv = rsqrtf(var + EPSF);
#pragma unroll
    for (int i = 0; i < 4; i++) {
        int c = t + i * 128;
        out[(long)row * Cn + c] = (y[i] - mu) * inv * g[c] + bta[c];
    }
}

// ---------------- launch ---------------------------------------------------
extern "C" void kernel_launch(void* const* d_in, const int* in_sizes, int n_in,
                              void* d_out, int out_size) {
    const float* x    = (const float*)d_in[0];
    const float* mask = (const float*)d_in[1];
    const float* wq   = (const float*)d_in[2];
    const float* bq   = (const float*)d_in[3];
    const float* wk   = (const float*)d_in[4];
    const float* bk   = (const float*)d_in[5];
    const float* wv   = (const float*)d_in[6];
    const float* bv   = (const float*)d_in[7];
    const float* wo   = (const float*)d_in[8];
    const float* bo   = (const float*)d_in[9];
    const float* relk = (const float*)d_in[10];
    const float* relv = (const float*)d_in[11];
    const float* ln1g = (const float*)d_in[12];
    const float* ln1b = (const float*)d_in[13];
    const float* w1   = (const float*)d_in[14];
    const float* b1   = (const float*)d_in[15];
    const float* w2   = (const float*)d_in[16];
    const float* b2   = (const float*)d_in[17];
    const float* ln2g = (const float*)d_in[18];
    const float* ln2b = (const float*)d_in[19];
    float* out = (float*)d_out;

    float *xt, *q, *k, *v, *ao, *tmp, *h;
    cudaGetSymbolAddress((void**)&xt,  g_xt);
    cudaGetSymbolAddress((void**)&q,   g_q);
    cudaGetSymbolAddress((void**)&k,   g_k);
    cudaGetSymbolAddress((void**)&v,   g_v);
    cudaGetSymbolAddress((void**)&ao,  g_ao);
    cudaGetSymbolAddress((void**)&tmp, g_tmp);
    cudaGetSymbolAddress((void**)&h,   g_h);

    cudaFuncSetAttribute((const void*)attn_tc_kernel,
                         cudaFuncAttributeMaxDynamicSharedMemorySize, ATTN2_SMEM_BYTES);
    cudaFuncSetAttribute((const void*)gemm_tf32<0>,
                         cudaFuncAttributeMaxDynamicSharedMemorySize, GEMM_SMEM_BYTES);
    cudaFuncSetAttribute((const void*)gemm_tf32<1>,
                         cudaFuncAttributeMaxDynamicSharedMemorySize, GEMM_SMEM_BYTES);
    cudaFuncSetAttribute((const void*)gemm_tf32<2>,
                         cudaFuncAttributeMaxDynamicSharedMemorySize, GEMM_SMEM_BYTES);
    cudaFuncSetAttribute((const void*)gemm_tf32<3>,
                         cudaFuncAttributeMaxDynamicSharedMemorySize, GEMM_SMEM_BYTES);

    transpose_in<<<dim3(Ln / 32, Cn / 32, Bn), dim3(32, 8)>>>(x, mask, xt);

    const dim3 gemmC(Cn / 128, Mrows / 128);    // N=512
    const dim3 gemmF(FCn / 128, Mrows / 128);   // N=2048

    for (int i = 0; i < NLn; i++) {
        const float* Wq = wq + (long)i * Cn * Cn;
        const float* Wk = wk + (long)i * Cn * Cn;
        const float* Wv = wv + (long)i * Cn * Cn;
        const float* Wo = wo + (long)i * Cn * Cn;
        const float* W1 = w1 + (long)i * FCn * Cn;
        const float* W2 = w2 + (long)i * Cn * FCn;

        gemm_tf32<1><<<gemmC, 256, GEMM_SMEM_BYTES>>>(xt, Wq, bq + i * Cn, nullptr, q, Cn, Cn, SCALEF);
        gemm_tf32<0><<<gemmC, 256, GEMM_SMEM_BYTES>>>(xt, Wk, bk + i * Cn, nullptr, k, Cn, Cn, 1.f);
        gemm_tf32<0><<<gemmC, 256, GEMM_SMEM_BYTES>>>(xt, Wv, bv + i * Cn, nullptr, v, Cn, Cn, 1.f);

        attn_tc_kernel<<<dim3(Ln / BQ, Hn, Bn), 256, ATTN2_SMEM_BYTES>>>(
            q, k, v, relk + i * 9 * Dn, relv + i * 9 * Dn, mask, ao);

        gemm_tf32<0><<<gemmC, 256, GEMM_SMEM_BYTES>>>(ao, Wo, bo + i * Cn, nullptr, tmp, Cn, Cn, 1.f);
        ln_kernel<<<Mrows, 128>>>(xt, tmp, ln1g + i * Cn, ln1b + i * Cn, xt);

        gemm_tf32<2><<<gemmF, 256, GEMM_SMEM_BYTES>>>(xt, W1, b1 + i * FCn, mask, h, FCn, Cn, 1.f);
        gemm_tf32<3><<<gemmC, 256, GEMM_SMEM_BYTES>>>(h, W2, b2 + i * Cn, mask, tmp, Cn, FCn, 1.f);
        ln_kernel<<<Mrows, 128>>>(xt, tmp, ln2g + i * Cn, ln2b + i * Cn, xt);
    }

    transpose_out<<<dim3(Ln / 32, Cn / 32, Bn), dim3(32, 8)>>>(xt, mask, out);
}